// round 4
// baseline (speedup 1.0000x reference)
#include <cuda_runtime.h>
#include <math.h>

// Problem constants
#define NN    20000     // nodes
#define DEG   16        // fixed in-degree (LSTM sequence length)
#define F     128       // IN == HID
#define G4    512       // 4*F gate width
#define TILE  64        // nodes per block
#define NT    256       // threads per block
#define KC4   16        // k4 (float4) per W chunk  -> 64 k floats per chunk, 2 chunks cover K=128
#define WSTRIDE 513     // float4 row stride for staged W chunk [KC4][WSTRIDE] (odd -> conflict-free)

// Scratch (allocation-free rule: __device__ globals)
__device__ float g_P [(size_t)NN * G4];   // 40.96 MB: precomputed input projections + bias
__device__ float g_H1[(size_t)NN * F];    // 10.24 MB: layer-1 output (post ReLU)

__device__ __forceinline__ float sigm(float x) { return 1.0f / (1.0f + __expf(-x)); }

// Stage W (row-major [rows][128]) chunk k = [k4base*4, k4base*4+64) into smem as
// float4 Wt4[k4][row] with row-stride WSTRIDE. Global reads coalesced (16 lanes x 16B
// contiguous per row), STS conflict-free (bank start = 4*((k4+row)%8) distinct per phase).
__device__ __forceinline__ void load_wchunk(float4* Wt4, const float* __restrict__ W,
                                            int rows, int k4base) {
    int total = rows * KC4;
    for (int idx = threadIdx.x; idx < total; idx += NT) {
        int row = idx >> 4;     // / KC4
        int k4  = idx & 15;     // % KC4
        Wt4[k4 * WSTRIDE + row] =
            *reinterpret_cast<const float4*>(W + (size_t)row * F + (size_t)(k4base + k4) * 4);
    }
}

// acc[i][g*4+uu] += sum_k Hs[node_i][k] * W[g*128 + uu*32 + ut][k] over this chunk.
// a-loads: warp-uniform broadcast LDS.128. b-loads: lanes stride-1 rows, conflict-free LDS.128.
__device__ __forceinline__ void gemm_chunk(float (&acc)[8][16],
                                           const float4* __restrict__ Wt4,
                                           const float4* __restrict__ Hs4,
                                           int nl0, int ut, int k4off) {
#pragma unroll 2
    for (int k4 = 0; k4 < KC4; ++k4) {
        float4 a[8];
#pragma unroll
        for (int i = 0; i < 8; ++i) a[i] = Hs4[(nl0 + i) * 32 + k4off + k4];
#pragma unroll
        for (int g = 0; g < 4; ++g) {
#pragma unroll
            for (int uu = 0; uu < 4; ++uu) {
                float4 b = Wt4[k4 * WSTRIDE + g * 128 + uu * 32 + ut];
                const int j = g * 4 + uu;
#pragma unroll
                for (int i = 0; i < 8; ++i) {
                    float s = acc[i][j];
                    s = fmaf(a[i].x, b.x, s);
                    s = fmaf(a[i].y, b.y, s);
                    s = fmaf(a[i].z, b.z, s);
                    s = fmaf(a[i].w, b.w, s);
                    acc[i][j] = s;
                }
            }
        }
    }
}

// ---------------------------------------------------------------------------
// proj: g_P[n][col] = sum_k X[n][k]*Wih[col][k] + bih[col] + bhh[col]
// ---------------------------------------------------------------------------
__global__ void __launch_bounds__(NT, 1)
proj_kernel(const float* __restrict__ Xin, int useH1,
            const float* __restrict__ Wih,
            const float* __restrict__ bih,
            const float* __restrict__ bhh) {
    extern __shared__ float smem[];
    float4* Hs4 = reinterpret_cast<float4*>(smem);
    float4* Wt4 = reinterpret_cast<float4*>(smem + TILE * F);

    const float* X = useH1 ? g_H1 : Xin;
    const int tid = threadIdx.x, ut = tid & 31, nt = tid >> 5;
    const int tile0 = blockIdx.x * TILE;
    const int nl0 = nt * 8;

    // Stage X tile into smem (coalesced float4)
    for (int idx = tid; idx < TILE * 32; idx += NT) {
        int r = idx >> 5, c4 = idx & 31;
        int n = tile0 + r;
        float4 v = make_float4(0.f, 0.f, 0.f, 0.f);
        if (n < NN) v = *reinterpret_cast<const float4*>(X + (size_t)n * F + c4 * 4);
        Hs4[idx] = v;
    }

    float acc[8][16];
#pragma unroll
    for (int g = 0; g < 4; ++g)
#pragma unroll
        for (int uu = 0; uu < 4; ++uu) {
            int col = g * 128 + uu * 32 + ut;
            float b0 = __ldg(bih + col) + __ldg(bhh + col);
#pragma unroll
            for (int i = 0; i < 8; ++i) acc[i][g * 4 + uu] = b0;
        }

#pragma unroll 1
    for (int c2 = 0; c2 < 2; ++c2) {
        __syncthreads();
        load_wchunk(Wt4, Wih, G4, c2 * KC4);
        __syncthreads();
        gemm_chunk(acc, Wt4, Hs4, nl0, ut, c2 * KC4);
    }

#pragma unroll
    for (int i = 0; i < 8; ++i) {
        int n = tile0 + nl0 + i;
        if (n < NN) {
#pragma unroll
            for (int g = 0; g < 4; ++g)
#pragma unroll
                for (int uu = 0; uu < 4; ++uu)
                    g_P[(size_t)n * G4 + g * 128 + uu * 32 + ut] = acc[i][g * 4 + uu];
        }
    }
}

// ---------------------------------------------------------------------------
// rec: 16-step LSTM recurrence on gathered projections + layer epilogue.
// LAYER==1: writes g_H1 = relu(x@Wself.T + hN@Wneigh.T + bneigh)
// LAYER==2: writes out[n] = sigmoid(h1[n].Wself + hN[n].Wneigh + b)
// ---------------------------------------------------------------------------
template <int LAYER>
__global__ void __launch_bounds__(NT, 1)
rec_kernel(const float* __restrict__ Xin,
           const int* __restrict__ nbr,
           const float* __restrict__ Whh,
           const float* __restrict__ Wself,
           const float* __restrict__ Wneigh,
           const float* __restrict__ bneigh,
           float* __restrict__ out) {
    extern __shared__ float smem[];
    float*  Hs  = smem;                                       // [64][128] h state
    float4* Hs4 = reinterpret_cast<float4*>(smem);
    float4* Wt4 = reinterpret_cast<float4*>(smem + TILE * F);

    const float* X = (LAYER == 1) ? Xin : g_H1;
    const int tid = threadIdx.x, ut = tid & 31, nt = tid >> 5;
    const int tile0 = blockIdx.x * TILE;
    const int nl0 = nt * 8;

    float c[8][4];
#pragma unroll
    for (int i = 0; i < 8; ++i)
#pragma unroll
        for (int uu = 0; uu < 4; ++uu) c[i][uu] = 0.0f;

#pragma unroll 1
    for (int t = 0; t < DEG; ++t) {
        float acc[8][16];
        // Gather: acc init = P[nbr[n][t]][gate cols]. Coalesced 128B per (node,gate,uu).
#pragma unroll
        for (int i = 0; i < 8; ++i) {
            int n = tile0 + nl0 + i;
            int jn = (n < NN) ? __ldg(nbr + (size_t)n * DEG + t) : 0;
            const float* Pr = g_P + (size_t)jn * G4;
#pragma unroll
            for (int g = 0; g < 4; ++g)
#pragma unroll
                for (int uu = 0; uu < 4; ++uu)
                    acc[i][g * 4 + uu] = __ldg(Pr + g * 128 + uu * 32 + ut);
        }
        // Recurrent GEMM: gates += h @ Whh.T   (skip at t=0, h==0)
        if (t > 0) {
#pragma unroll 1
            for (int c2 = 0; c2 < 2; ++c2) {
                __syncthreads();
                load_wchunk(Wt4, Whh, G4, c2 * KC4);
                __syncthreads();
                gemm_chunk(acc, Wt4, Hs4, nl0, ut, c2 * KC4);
            }
        }
        // Elementwise LSTM cell (gate order i,f,g,o)
#pragma unroll
        for (int i = 0; i < 8; ++i)
#pragma unroll
            for (int uu = 0; uu < 4; ++uu) {
                float ig = sigm(acc[i][0 + uu]);
                float fg = sigm(acc[i][4 + uu]);
                float gg = tanhf(acc[i][8 + uu]);
                float og = sigm(acc[i][12 + uu]);
                float cc = fmaf(fg, c[i][uu], ig * gg);
                c[i][uu] = cc;
                Hs[(nl0 + i) * F + uu * 32 + ut] = og * tanhf(cc);
            }
        __syncwarp();  // H rows are warp-private; next reads ordered by chunk syncthreads
    }

    if (LAYER == 1) {
        float oacc[8][4];
#pragma unroll
        for (int uu = 0; uu < 4; ++uu) {
            float b0 = __ldg(bneigh + uu * 32 + ut);
#pragma unroll
            for (int i = 0; i < 8; ++i) oacc[i][uu] = b0;
        }
        // self term: X rows from global
#pragma unroll 1
        for (int c2 = 0; c2 < 2; ++c2) {
            __syncthreads();
            load_wchunk(Wt4, Wself, F, c2 * KC4);
            __syncthreads();
#pragma unroll 2
            for (int k4 = 0; k4 < KC4; ++k4) {
                float4 a[8];
#pragma unroll
                for (int i = 0; i < 8; ++i) {
                    int n = tile0 + nl0 + i;
                    a[i] = (n < NN)
                         ? *reinterpret_cast<const float4*>(X + (size_t)n * F + (c2 * KC4 + k4) * 4)
                         : make_float4(0.f, 0.f, 0.f, 0.f);
                }
#pragma unroll
                for (int uu = 0; uu < 4; ++uu) {
                    float4 b = Wt4[k4 * WSTRIDE + uu * 32 + ut];
#pragma unroll
                    for (int i = 0; i < 8; ++i)
                        oacc[i][uu] = fmaf(a[i].x, b.x, fmaf(a[i].y, b.y,
                                      fmaf(a[i].z, b.z, fmaf(a[i].w, b.w, oacc[i][uu]))));
                }
            }
        }
        // neighbor term: final h from smem
#pragma unroll 1
        for (int c2 = 0; c2 < 2; ++c2) {
            __syncthreads();
            load_wchunk(Wt4, Wneigh, F, c2 * KC4);
            __syncthreads();
#pragma unroll 2
            for (int k4 = 0; k4 < KC4; ++k4) {
                float4 a[8];
#pragma unroll
                for (int i = 0; i < 8; ++i) a[i] = Hs4[(nl0 + i) * 32 + c2 * KC4 + k4];
#pragma unroll
                for (int uu = 0; uu < 4; ++uu) {
                    float4 b = Wt4[k4 * WSTRIDE + uu * 32 + ut];
#pragma unroll
                    for (int i = 0; i < 8; ++i)
                        oacc[i][uu] = fmaf(a[i].x, b.x, fmaf(a[i].y, b.y,
                                      fmaf(a[i].z, b.z, fmaf(a[i].w, b.w, oacc[i][uu]))));
                }
            }
        }
#pragma unroll
        for (int i = 0; i < 8; ++i) {
            int n = tile0 + nl0 + i;
            if (n < NN) {
#pragma unroll
                for (int uu = 0; uu < 4; ++uu)
                    g_H1[(size_t)n * F + uu * 32 + ut] = fmaxf(oacc[i][uu], 0.0f);
            }
        }
    } else {
        // OUT=1 epilogue: per-node dot products, warp butterfly reduce
        float part[8];
#pragma unroll
        for (int i = 0; i < 8; ++i) part[i] = 0.0f;
#pragma unroll
        for (int uu = 0; uu < 4; ++uu) {
            int u = uu * 32 + ut;
            float wn = __ldg(Wneigh + u);
            float ws = __ldg(Wself + u);
#pragma unroll
            for (int i = 0; i < 8; ++i) {
                int n = tile0 + nl0 + i;
                float hx = Hs[(nl0 + i) * F + u];
                float xx = (n < NN) ? __ldg(X + (size_t)n * F + u) : 0.0f;
                part[i] = fmaf(hx, wn, fmaf(xx, ws, part[i]));
            }
        }
        float b0 = __ldg(bneigh);
#pragma unroll
        for (int off = 16; off > 0; off >>= 1)
#pragma unroll
            for (int i = 0; i < 8; ++i)
                part[i] += __shfl_xor_sync(0xffffffffu, part[i], off);
        if (ut == 0) {
#pragma unroll
            for (int i = 0; i < 8; ++i) {
                int n = tile0 + nl0 + i;
                if (n < NN) out[n] = sigm(part[i] + b0);
            }
        }
    }
}

extern "C" void kernel_launch(void* const* d_in, const int* in_sizes, int n_in,
                              void* d_out, int out_size) {
    const float* x       = (const float*)d_in[0];
    const int*   nbr     = (const int*)  d_in[1];
    const float* Wih1    = (const float*)d_in[2];
    const float* Whh1    = (const float*)d_in[3];
    const float* bih1    = (const float*)d_in[4];
    const float* bhh1    = (const float*)d_in[5];
    const float* Wself1  = (const float*)d_in[6];
    const float* Wneigh1 = (const float*)d_in[7];
    const float* bneigh1 = (const float*)d_in[8];
    const float* Wih2    = (const float*)d_in[9];
    const float* Whh2    = (const float*)d_in[10];
    const float* bih2    = (const float*)d_in[11];
    const float* bhh2    = (const float*)d_in[12];
    const float* Wself2  = (const float*)d_in[13];
    const float* Wneigh2 = (const float*)d_in[14];
    const float* bneigh2 = (const float*)d_in[15];
    float* out = (float*)d_out;

    const int    nb   = (NN + TILE - 1) / TILE;          // 313 blocks
    const size_t smem = (size_t)TILE * F * 4 + (size_t)KC4 * WSTRIDE * 16;  // 164,096 B

    cudaFuncSetAttribute(proj_kernel,   cudaFuncAttributeMaxDynamicSharedMemorySize, (int)smem);
    cudaFuncSetAttribute(rec_kernel<1>, cudaFuncAttributeMaxDynamicSharedMemorySize, (int)smem);
    cudaFuncSetAttribute(rec_kernel<2>, cudaFuncAttributeMaxDynamicSharedMemorySize, (int)smem);

    // Layer 1
    proj_kernel<<<nb, NT, smem>>>(x, 0, Wih1, bih1, bhh1);
    rec_kernel<1><<<nb, NT, smem>>>(x, nbr, Whh1, Wself1, Wneigh1, bneigh1, nullptr);
    // Layer 2
    proj_kernel<<<nb, NT, smem>>>(nullptr, 1, Wih2, bih2, bhh2);
    rec_kernel<2><<<nb, NT, smem>>>(nullptr, nbr, Whh2, Wself2, Wneigh2, bneigh2, out);
}

// round 5
// speedup vs baseline: 3.8665x; 3.8665x over previous
#include <cuda_runtime.h>
#include <math.h>
#include <stdint.h>

// Problem constants
#define NN    20000
#define DEG   16
#define F     128
#define G4    512
#define TILE  64
#define NT    256
#define PH    132        // Hs pitch (floats); 132 mod 32 = 4 -> conflict-free frag LDS
#define PW    68         // Wc pitch (u32) for K=64 tf32 chunks; 68 mod 32 = 4
#define PNB   17         // nbr tile pitch

// smem layout (float offsets)
#define SH_HS 0
#define SH_NB (TILE*PH)                 // 8448
#define SH_WC (SH_NB + TILE*PNB)        // 9536
#define SMEM_FLOATS (SH_WC + G4*PW)     // 44352
#define SMEM_BYTES  (SMEM_FLOATS*4)     // 177,408 B

__device__ float g_P [(size_t)NN * G4];   // projections + bias (fp32, exact)
__device__ float g_H1[(size_t)NN * F];    // layer-1 output

__device__ __forceinline__ uint32_t f2tf(float f) {
    uint32_t u; asm("cvt.rna.tf32.f32 %0, %1;" : "=r"(u) : "f"(f)); return u;
}
__device__ __forceinline__ void mma8(float4& d, uint32_t a0, uint32_t a1, uint32_t a2,
                                     uint32_t a3, uint32_t b0, uint32_t b1) {
    asm volatile(
        "mma.sync.aligned.m16n8k8.row.col.f32.tf32.tf32.f32 "
        "{%0,%1,%2,%3}, {%4,%5,%6,%7}, {%8,%9}, {%0,%1,%2,%3};"
        : "+f"(d.x), "+f"(d.y), "+f"(d.z), "+f"(d.w)
        : "r"(a0), "r"(a1), "r"(a2), "r"(a3), "r"(b0), "r"(b1));
}
// sigmoid via MUFU tanh (0.5x scaling halves approx error)
__device__ __forceinline__ float sigm_f(float x) {
    float y, h = 0.5f * x;
    asm("tanh.approx.f32 %0, %1;" : "=f"(y) : "f"(h));
    return fmaf(0.5f, y, 0.5f);
}
// precise tanh for the c-accumulation path
__device__ __forceinline__ float tanh_p(float x) {
    float e = __expf(2.0f * x);
    return 1.0f - __fdividef(2.0f, e + 1.0f);
}
__device__ __forceinline__ float sigm_p(float x) { return 1.0f / (1.0f + __expf(-x)); }

// Stage a K=64 chunk of W (rows=512 gate cols) into Wc[q][k] (tf32), pitch PW.
// PERM=1: slot q holds gate-interleaved column so each warp's 64-col slice
// = 16 units x 4 gates, making the LSTM elementwise warp-local.
template <int PERM>
__device__ __forceinline__ void stage_w_tf32(uint32_t* Wc, const float* __restrict__ W, int k0) {
    for (int idx = threadIdx.x; idx < G4 * 16; idx += NT) {
        int q = idx >> 4, k4 = idx & 15;
        int oc;
        if (PERM) {
            int w = q >> 6, p = q & 63;
            oc = ((p >> 3) & 3) * 128 + w * 16 + (p & 7) + ((p >> 5) << 3);
        } else {
            oc = q;
        }
        float4 v = *reinterpret_cast<const float4*>(W + (size_t)oc * F + k0 + k4 * 4);
        uint4 s;
        s.x = f2tf(v.x); s.y = f2tf(v.y); s.z = f2tf(v.z); s.w = f2tf(v.w);
        *reinterpret_cast<uint4*>(Wc + q * PW + k4 * 4) = s;
    }
}

// One K=64 chunk of the 64x512 GEMM: acc += A(Hs, fp32->tf32) @ B(Wc, tf32)
__device__ __forceinline__ void gemm64(float4 (&acc)[4][8], const uint32_t* __restrict__ Wc,
                                       const float* __restrict__ Hs, int kbase,
                                       int gid, int tig, int wslice) {
#pragma unroll
    for (int k8 = 0; k8 < 8; ++k8) {
        uint32_t bb[8][2];
#pragma unroll
        for (int nj = 0; nj < 8; ++nj) {
            const uint32_t* bp = Wc + (wslice + nj * 8 + gid) * PW + k8 * 8 + tig;
            bb[nj][0] = bp[0];
            bb[nj][1] = bp[4];
        }
#pragma unroll
        for (int mi = 0; mi < 4; ++mi) {
            const float* ap = Hs + (mi * 16 + gid) * PH + kbase + k8 * 8 + tig;
            uint32_t a0 = f2tf(ap[0]);
            uint32_t a1 = f2tf(ap[8 * PH]);
            uint32_t a2 = f2tf(ap[4]);
            uint32_t a3 = f2tf(ap[8 * PH + 4]);
#pragma unroll
            for (int nj = 0; nj < 8; ++nj)
                mma8(acc[mi][nj], a0, a1, a2, a3, bb[nj][0], bb[nj][1]);
        }
    }
}

// ---------------------------------------------------------------------------
// proj: g_P[n][col] = X[n] @ Wih[col] + bih[col] + bhh[col]   (tf32 mma)
// ---------------------------------------------------------------------------
__global__ void __launch_bounds__(NT, 1)
proj_kernel(const float* __restrict__ Xin, int useH1,
            const float* __restrict__ Wih,
            const float* __restrict__ bih, const float* __restrict__ bhh) {
    extern __shared__ float smem[];
    float* Hs = smem + SH_HS;
    uint32_t* Wc = reinterpret_cast<uint32_t*>(smem + SH_WC);

    const float* X = useH1 ? g_H1 : Xin;
    const int tid = threadIdx.x, lane = tid & 31, w = tid >> 5;
    const int gid = lane >> 2, tig = lane & 3;
    const int tile0 = blockIdx.x * TILE;

    for (int idx = tid; idx < TILE * 32; idx += NT) {
        int r = idx >> 5, c4 = idx & 31;
        int n = tile0 + r;
        float4 v = make_float4(0.f, 0.f, 0.f, 0.f);
        if (n < NN) v = *reinterpret_cast<const float4*>(X + (size_t)n * F + c4 * 4);
        *reinterpret_cast<float4*>(Hs + r * PH + c4 * 4) = v;
    }

    float4 acc[4][8];
#pragma unroll
    for (int nj = 0; nj < 8; ++nj) {
        int col = w * 64 + nj * 8 + 2 * tig;
        float b0 = __ldg(bih + col) + __ldg(bhh + col);
        float b1 = __ldg(bih + col + 1) + __ldg(bhh + col + 1);
#pragma unroll
        for (int mi = 0; mi < 4; ++mi) acc[mi][nj] = make_float4(b0, b1, b0, b1);
    }

#pragma unroll 1
    for (int c2 = 0; c2 < 2; ++c2) {
        __syncthreads();
        stage_w_tf32<0>(Wc, Wih, c2 * 64);
        __syncthreads();
        gemm64(acc, Wc, Hs, c2 * 64, gid, tig, w * 64);
    }

#pragma unroll
    for (int mi = 0; mi < 4; ++mi) {
        int r0 = mi * 16 + gid;
        int n0 = tile0 + r0, n1 = n0 + 8;
#pragma unroll
        for (int nj = 0; nj < 8; ++nj) {
            int col = w * 64 + nj * 8 + 2 * tig;
            if (n0 < NN)
                *reinterpret_cast<float2*>(g_P + (size_t)n0 * G4 + col) =
                    make_float2(acc[mi][nj].x, acc[mi][nj].y);
            if (n1 < NN)
                *reinterpret_cast<float2*>(g_P + (size_t)n1 * G4 + col) =
                    make_float2(acc[mi][nj].z, acc[mi][nj].w);
        }
    }
}

// ---------------------------------------------------------------------------
// rec: 16-step LSTM recurrence (tf32 mma, permuted gate cols) + epilogue
// ---------------------------------------------------------------------------
template <int LAYER>
__global__ void __launch_bounds__(NT, 1)
rec_kernel(const float* __restrict__ Xin, const int* __restrict__ nbr,
           const float* __restrict__ Whh, const float* __restrict__ Wself,
           const float* __restrict__ Wneigh, const float* __restrict__ bneigh,
           float* __restrict__ out) {
    extern __shared__ float smem[];
    float* Hs = smem + SH_HS;
    int* Nb = reinterpret_cast<int*>(smem + SH_NB);
    uint32_t* Wc = reinterpret_cast<uint32_t*>(smem + SH_WC);
    float* Wcf = smem + SH_WC;   // epilogue fp32 view, pitch PH

    const float* X = (LAYER == 1) ? Xin : g_H1;
    const int tid = threadIdx.x, lane = tid & 31, w = tid >> 5;
    const int gid = lane >> 2, tig = lane & 3;
    const int tile0 = blockIdx.x * TILE;

    // Stage neighbor indices once
    for (int idx = tid; idx < TILE * DEG; idx += NT) {
        int r = idx >> 4, t = idx & 15;
        int n = tile0 + r;
        Nb[r * PNB + t] = (n < NN) ? __ldg(nbr + (size_t)n * DEG + t) : 0;
    }
    __syncthreads();

    // permuted col -> original P col (per thread, e=0 element of each pair)
    int ocb[8];
#pragma unroll
    for (int nj = 0; nj < 8; ++nj)
        ocb[nj] = (nj & 3) * 128 + w * 16 + ((nj >> 2) << 3) + 2 * tig;

    float4 cst[4][2];
#pragma unroll
    for (int mi = 0; mi < 4; ++mi) {
        cst[mi][0] = make_float4(0.f, 0.f, 0.f, 0.f);
        cst[mi][1] = make_float4(0.f, 0.f, 0.f, 0.f);
    }

#pragma unroll 1
    for (int t = 0; t < DEG; ++t) {
        float4 acc[4][8];
        // Gather P (fp32, exact) straight into mma accumulators
#pragma unroll
        for (int mi = 0; mi < 4; ++mi) {
            int r0 = mi * 16 + gid;
            const float* P0 = g_P + (size_t)Nb[r0 * PNB + t] * G4;
            const float* P1 = g_P + (size_t)Nb[(r0 + 8) * PNB + t] * G4;
#pragma unroll
            for (int nj = 0; nj < 8; ++nj) {
                float2 u = *reinterpret_cast<const float2*>(P0 + ocb[nj]);
                float2 v = *reinterpret_cast<const float2*>(P1 + ocb[nj]);
                acc[mi][nj] = make_float4(u.x, u.y, v.x, v.y);
            }
        }
        if (t > 0) {
#pragma unroll 1
            for (int c2 = 0; c2 < 2; ++c2) {
                __syncthreads();
                stage_w_tf32<1>(Wc, Whh, c2 * 64);
                __syncthreads();
                gemm64(acc, Wc, Hs, c2 * 64, gid, tig, w * 64);
            }
        }
        // Warp-local LSTM elementwise: each thread holds i,f,g,o of its (node,unit)s
#pragma unroll
        for (int mi = 0; mi < 4; ++mi) {
            int r0 = mi * 16 + gid;
#pragma unroll
            for (int uh = 0; uh < 2; ++uh) {
                float4 I  = acc[mi][uh * 4 + 0];
                float4 Fg = acc[mi][uh * 4 + 1];
                float4 G  = acc[mi][uh * 4 + 2];
                float4 O  = acc[mi][uh * 4 + 3];
                float4& C = cst[mi][uh];
                float c0 = fmaf(sigm_f(Fg.x), C.x, sigm_f(I.x) * tanh_p(G.x));
                float c1 = fmaf(sigm_f(Fg.y), C.y, sigm_f(I.y) * tanh_p(G.y));
                float c2v = fmaf(sigm_f(Fg.z), C.z, sigm_f(I.z) * tanh_p(G.z));
                float c3 = fmaf(sigm_f(Fg.w), C.w, sigm_f(I.w) * tanh_p(G.w));
                C = make_float4(c0, c1, c2v, c3);
                int unit = w * 16 + uh * 8 + 2 * tig;
                *reinterpret_cast<float2*>(Hs + r0 * PH + unit) =
                    make_float2(sigm_f(O.x) * tanh_p(c0), sigm_f(O.y) * tanh_p(c1));
                *reinterpret_cast<float2*>(Hs + (r0 + 8) * PH + unit) =
                    make_float2(sigm_f(O.z) * tanh_p(c2v), sigm_f(O.w) * tanh_p(c3));
            }
        }
    }

    const int nl0 = w * 8;
    if (LAYER == 1) {
        float oacc[8][4];
#pragma unroll
        for (int uu = 0; uu < 4; ++uu) {
            float b0 = __ldg(bneigh + uu * 32 + lane);
#pragma unroll
            for (int i = 0; i < 8; ++i) oacc[i][uu] = b0;
        }
        // self term (fp32 exact)
        __syncthreads();
        for (int idx = tid; idx < F * 32; idx += NT) {
            int rr = idx >> 5, c4 = idx & 31;
            *reinterpret_cast<float4*>(Wcf + rr * PH + c4 * 4) =
                *reinterpret_cast<const float4*>(Wself + (size_t)rr * F + c4 * 4);
        }
        __syncthreads();
#pragma unroll 2
        for (int k4 = 0; k4 < 32; ++k4) {
            float4 a[8];
#pragma unroll
            for (int i = 0; i < 8; ++i) {
                int n = tile0 + nl0 + i;
                a[i] = (n < NN) ? *reinterpret_cast<const float4*>(X + (size_t)n * F + k4 * 4)
                                : make_float4(0.f, 0.f, 0.f, 0.f);
            }
#pragma unroll
            for (int uu = 0; uu < 4; ++uu) {
                float4 b = *reinterpret_cast<const float4*>(Wcf + (uu * 32 + lane) * PH + k4 * 4);
#pragma unroll
                for (int i = 0; i < 8; ++i)
                    oacc[i][uu] = fmaf(a[i].x, b.x, fmaf(a[i].y, b.y,
                                  fmaf(a[i].z, b.z, fmaf(a[i].w, b.w, oacc[i][uu]))));
            }
        }
        // neighbor term
        __syncthreads();
        for (int idx = tid; idx < F * 32; idx += NT) {
            int rr = idx >> 5, c4 = idx & 31;
            *reinterpret_cast<float4*>(Wcf + rr * PH + c4 * 4) =
                *reinterpret_cast<const float4*>(Wneigh + (size_t)rr * F + c4 * 4);
        }
        __syncthreads();
#pragma unroll 2
        for (int k4 = 0; k4 < 32; ++k4) {
            float4 a[8];
#pragma unroll
            for (int i = 0; i < 8; ++i)
                a[i] = *reinterpret_cast<const float4*>(Hs + (nl0 + i) * PH + k4 * 4);
#pragma unroll
            for (int uu = 0; uu < 4; ++uu) {
                float4 b = *reinterpret_cast<const float4*>(Wcf + (uu * 32 + lane) * PH + k4 * 4);
#pragma unroll
                for (int i = 0; i < 8; ++i)
                    oacc[i][uu] = fmaf(a[i].x, b.x, fmaf(a[i].y, b.y,
                                  fmaf(a[i].z, b.z, fmaf(a[i].w, b.w, oacc[i][uu]))));
            }
        }
#pragma unroll
        for (int i = 0; i < 8; ++i) {
            int n = tile0 + nl0 + i;
            if (n < NN) {
#pragma unroll
                for (int uu = 0; uu < 4; ++uu)
                    g_H1[(size_t)n * F + uu * 32 + lane] = fmaxf(oacc[i][uu], 0.0f);
            }
        }
    } else {
        __syncthreads();   // other warps' units in Hs
        float part[8];
#pragma unroll
        for (int i = 0; i < 8; ++i) part[i] = 0.0f;
#pragma unroll
        for (int uu = 0; uu < 4; ++uu) {
            int u = uu * 32 + lane;
            float wn = __ldg(Wneigh + u);
            float ws = __ldg(Wself + u);
#pragma unroll
            for (int i = 0; i < 8; ++i) {
                int n = tile0 + nl0 + i;
                float hx = Hs[(nl0 + i) * PH + u];
                float xx = (n < NN) ? __ldg(X + (size_t)n * F + u) : 0.0f;
                part[i] = fmaf(hx, wn, fmaf(xx, ws, part[i]));
            }
        }
        float b0 = __ldg(bneigh);
#pragma unroll
        for (int off = 16; off > 0; off >>= 1)
#pragma unroll
            for (int i = 0; i < 8; ++i)
                part[i] += __shfl_xor_sync(0xffffffffu, part[i], off);
        if (lane == 0) {
#pragma unroll
            for (int i = 0; i < 8; ++i) {
                int n = tile0 + nl0 + i;
                if (n < NN) out[n] = sigm_p(part[i] + b0);
            }
        }
    }
}

extern "C" void kernel_launch(void* const* d_in, const int* in_sizes, int n_in,
                              void* d_out, int out_size) {
    const float* x       = (const float*)d_in[0];
    const int*   nbr     = (const int*)  d_in[1];
    const float* Wih1    = (const float*)d_in[2];
    const float* Whh1    = (const float*)d_in[3];
    const float* bih1    = (const float*)d_in[4];
    const float* bhh1    = (const float*)d_in[5];
    const float* Wself1  = (const float*)d_in[6];
    const float* Wneigh1 = (const float*)d_in[7];
    const float* bneigh1 = (const float*)d_in[8];
    const float* Wih2    = (const float*)d_in[9];
    const float* Whh2    = (const float*)d_in[10];
    const float* bih2    = (const float*)d_in[11];
    const float* bhh2    = (const float*)d_in[12];
    const float* Wself2  = (const float*)d_in[13];
    const float* Wneigh2 = (const float*)d_in[14];
    const float* bneigh2 = (const float*)d_in[15];
    float* out = (float*)d_out;

    const int nb = (NN + TILE - 1) / TILE;   // 313

    cudaFuncSetAttribute(proj_kernel,   cudaFuncAttributeMaxDynamicSharedMemorySize, SMEM_BYTES);
    cudaFuncSetAttribute(rec_kernel<1>, cudaFuncAttributeMaxDynamicSharedMemorySize, SMEM_BYTES);
    cudaFuncSetAttribute(rec_kernel<2>, cudaFuncAttributeMaxDynamicSharedMemorySize, SMEM_BYTES);

    proj_kernel<<<nb, NT, SMEM_BYTES>>>(x, 0, Wih1, bih1, bhh1);
    rec_kernel<1><<<nb, NT, SMEM_BYTES>>>(x, nbr, Whh1, Wself1, Wneigh1, bneigh1, nullptr);
    proj_kernel<<<nb, NT, SMEM_BYTES>>>(nullptr, 1, Wih2, bih2, bhh2);
    rec_kernel<2><<<nb, NT, SMEM_BYTES>>>(nullptr, nbr, Whh2, Wself2, Wneigh2, bneigh2, out);
}

// round 8
// speedup vs baseline: 5.3824x; 1.3920x over previous
#include <cuda_runtime.h>
#include <math.h>
#include <stdint.h>

// Problem constants
#define NN    20000
#define DEG   16
#define F     128
#define G4    512
#define TILE  64
#define NT    256

// ---------------- proj kernel layout (round-5, unchanged) ----------------
#define PH    132
#define PW    68
#define P_SH_HS 0
#define P_SH_WC (TILE*PH + TILE*17)            // 9536
#define P_SMEM_FLOATS (P_SH_WC + G4*PW)        // 44352
#define P_SMEM_BYTES  (P_SMEM_FLOATS*4)        // 177408

// ---------------- rec kernel (2-CTA cluster) layout, u32 indices ---------
#define PH2   132     // Hs pitch (u32); 132 mod 32 = 4 -> conflict-free frags
#define PW2   132     // Wc pitch (u32)
#define R_NB  0                                // 64*17 = 1088 ints
#define R_HS  (TILE*17)                        // 1088
#define R_HSBUF (TILE*PH2)                     // 8448 u32 per buffer
#define R_WC  (R_HS + 2*R_HSBUF)               // 17984
#define R_TOTAL (R_WC + 256*PW2)               // 51776 u32
#define R_BYTES (R_TOTAL*4)                    // 207104 B

__device__ float g_P [(size_t)NN * G4];   // projections + bias (fp32, exact)
__device__ float g_H1[(size_t)NN * F];    // layer-1 output

// ---------------- helpers ----------------
__device__ __forceinline__ uint32_t f2tf(float f) {
    uint32_t u; asm("cvt.rna.tf32.f32 %0, %1;" : "=r"(u) : "f"(f)); return u;
}
__device__ __forceinline__ void mma8(float4& d, uint32_t a0, uint32_t a1, uint32_t a2,
                                     uint32_t a3, uint32_t b0, uint32_t b1) {
    asm volatile(
        "mma.sync.aligned.m16n8k8.row.col.f32.tf32.tf32.f32 "
        "{%0,%1,%2,%3}, {%4,%5,%6,%7}, {%8,%9}, {%0,%1,%2,%3};"
        : "+f"(d.x), "+f"(d.y), "+f"(d.z), "+f"(d.w)
        : "r"(a0), "r"(a1), "r"(a2), "r"(a3), "r"(b0), "r"(b1));
}
__device__ __forceinline__ float sigm_f(float x) {
    float y, h = 0.5f * x;
    asm("tanh.approx.f32 %0, %1;" : "=f"(y) : "f"(h));
    return fmaf(0.5f, y, 0.5f);
}
__device__ __forceinline__ float tanh_f(float x) {
    float y; asm("tanh.approx.f32 %0, %1;" : "=f"(y) : "f"(x)); return y;
}
__device__ __forceinline__ float sigm_p(float x) { return 1.0f / (1.0f + __expf(-x)); }

__device__ __forceinline__ uint32_t ctarank() {
    uint32_t r; asm("mov.u32 %0, %%cluster_ctarank;" : "=r"(r)); return r;
}
__device__ __forceinline__ uint32_t smem_u32(const void* p) {
    uint32_t a;
    asm("{ .reg .u64 t; cvta.to.shared.u64 t, %1; cvt.u32.u64 %0, t; }" : "=r"(a) : "l"(p));
    return a;
}
__device__ __forceinline__ uint32_t mapa_u32(uint32_t addr, uint32_t rank) {
    uint32_t r; asm("mapa.shared::cluster.u32 %0, %1, %2;" : "=r"(r) : "r"(addr), "r"(rank));
    return r;
}
__device__ __forceinline__ void st_dsmem64(uint32_t addr, unsigned long long v) {
    asm volatile("st.shared::cluster.u64 [%0], %1;" :: "r"(addr), "l"(v) : "memory");
}
#define CLUSTER_SYNC() do { \
    asm volatile("barrier.cluster.arrive.aligned;" ::: "memory"); \
    asm volatile("barrier.cluster.wait.aligned;" ::: "memory"); } while (0)

// ===========================================================================
// proj: g_P[n][col] = X[n] @ Wih[col] + bih[col] + bhh[col]   (round-5 code)
// ===========================================================================
template <int PERM>
__device__ __forceinline__ void stage_w_tf32(uint32_t* Wc, const float* __restrict__ W, int k0) {
    for (int idx = threadIdx.x; idx < G4 * 16; idx += NT) {
        int q = idx >> 4, k4 = idx & 15;
        int oc = q;
        (void)PERM;
        float4 v = *reinterpret_cast<const float4*>(W + (size_t)oc * F + k0 + k4 * 4);
        uint4 s;
        s.x = f2tf(v.x); s.y = f2tf(v.y); s.z = f2tf(v.z); s.w = f2tf(v.w);
        *reinterpret_cast<uint4*>(Wc + q * PW + k4 * 4) = s;
    }
}

__device__ __forceinline__ void gemm64p(float4 (&acc)[4][8], const uint32_t* __restrict__ Wc,
                                        const float* __restrict__ Hs, int kbase,
                                        int gid, int tig, int wslice) {
#pragma unroll
    for (int k8 = 0; k8 < 8; ++k8) {
        uint32_t bb[8][2];
#pragma unroll
        for (int nj = 0; nj < 8; ++nj) {
            const uint32_t* bp = Wc + (wslice + nj * 8 + gid) * PW + k8 * 8 + tig;
            bb[nj][0] = bp[0];
            bb[nj][1] = bp[4];
        }
#pragma unroll
        for (int mi = 0; mi < 4; ++mi) {
            const float* ap = Hs + (mi * 16 + gid) * PH + kbase + k8 * 8 + tig;
            uint32_t a0 = f2tf(ap[0]);
            uint32_t a1 = f2tf(ap[8 * PH]);
            uint32_t a2 = f2tf(ap[4]);
            uint32_t a3 = f2tf(ap[8 * PH + 4]);
#pragma unroll
            for (int nj = 0; nj < 8; ++nj)
                mma8(acc[mi][nj], a0, a1, a2, a3, bb[nj][0], bb[nj][1]);
        }
    }
}

__global__ void __launch_bounds__(NT, 1)
proj_kernel(const float* __restrict__ Xin, int useH1,
            const float* __restrict__ Wih,
            const float* __restrict__ bih, const float* __restrict__ bhh) {
    extern __shared__ float smem[];
    float* Hs = smem + P_SH_HS;
    uint32_t* Wc = reinterpret_cast<uint32_t*>(smem + P_SH_WC);

    const float* X = useH1 ? g_H1 : Xin;
    const int tid = threadIdx.x, lane = tid & 31, w = tid >> 5;
    const int gid = lane >> 2, tig = lane & 3;
    const int tile0 = blockIdx.x * TILE;

    for (int idx = tid; idx < TILE * 32; idx += NT) {
        int r = idx >> 5, c4 = idx & 31;
        int n = tile0 + r;
        float4 v = make_float4(0.f, 0.f, 0.f, 0.f);
        if (n < NN) v = *reinterpret_cast<const float4*>(X + (size_t)n * F + c4 * 4);
        *reinterpret_cast<float4*>(Hs + r * PH + c4 * 4) = v;
    }

    float4 acc[4][8];
#pragma unroll
    for (int nj = 0; nj < 8; ++nj) {
        int col = w * 64 + nj * 8 + 2 * tig;
        float b0 = __ldg(bih + col) + __ldg(bhh + col);
        float b1 = __ldg(bih + col + 1) + __ldg(bhh + col + 1);
#pragma unroll
        for (int mi = 0; mi < 4; ++mi) acc[mi][nj] = make_float4(b0, b1, b0, b1);
    }

#pragma unroll 1
    for (int c2 = 0; c2 < 2; ++c2) {
        __syncthreads();
        stage_w_tf32<0>(Wc, Wih, c2 * 64);
        __syncthreads();
        gemm64p(acc, Wc, Hs, c2 * 64, gid, tig, w * 64);
    }

#pragma unroll
    for (int mi = 0; mi < 4; ++mi) {
        int r0 = mi * 16 + gid;
        int n0 = tile0 + r0, n1 = n0 + 8;
#pragma unroll
        for (int nj = 0; nj < 8; ++nj) {
            int col = w * 64 + nj * 8 + 2 * tig;
            if (n0 < NN)
                *reinterpret_cast<float2*>(g_P + (size_t)n0 * G4 + col) =
                    make_float2(acc[mi][nj].x, acc[mi][nj].y);
            if (n1 < NN)
                *reinterpret_cast<float2*>(g_P + (size_t)n1 * G4 + col) =
                    make_float2(acc[mi][nj].z, acc[mi][nj].w);
        }
    }
}

// ===========================================================================
// rec: 2-CTA cluster. Each CTA owns 64 hidden units; Whh slice (128 KB tf32)
// resident in smem for all 16 steps; h halves exchanged via DSMEM each step.
// ===========================================================================
template <int LAYER>
__global__ void __launch_bounds__(NT, 1) __cluster_dims__(2, 1, 1)
rec_kernel(const float* __restrict__ Xin, const int* __restrict__ nbr,
           const float* __restrict__ Whh, const float* __restrict__ Wself,
           const float* __restrict__ Wneigh, const float* __restrict__ bneigh,
           float* __restrict__ out) {
    extern __shared__ uint32_t smemU[];
    int*       Nb = reinterpret_cast<int*>(smemU + R_NB);
    uint32_t*  HsB = smemU + R_HS;                 // 2 x [64][PH2] (tf32 bits)
    uint32_t*  Wc  = smemU + R_WC;                 // 256 x PW2 (resident tf32 Whh slice)

    const float* X = (LAYER == 1) ? Xin : g_H1;
    const int tid = threadIdx.x, lane = tid & 31, w = tid >> 5;
    const int gid = lane >> 2, tig = lane & 3;
    const uint32_t rank = ctarank();
    const int tile0 = (blockIdx.x >> 1) * TILE;

    // DSMEM base of peer's Hs region (byte address)
    const uint32_t myHsByte = smem_u32(HsB);
    const uint32_t peerHsByte = mapa_u32(myHsByte, rank ^ 1u);

    // Stage neighbor indices
    for (int idx = tid; idx < TILE * DEG; idx += NT) {
        int r = idx >> 4, t = idx & 15;
        int n = tile0 + r;
        Nb[r * 17 + t] = (n < NN) ? __ldg(nbr + (size_t)n * DEG + t) : 0;
    }
    // Stage this CTA's 256-col permuted Whh slice (ONCE).
    // col q = w*32 + gate*8 + uoff  ->  original row gate*128 + rank*64 + w*8 + uoff
    for (int idx = tid; idx < 256 * 32; idx += NT) {
        int q = idx >> 5, k4 = idx & 31;
        int p = q & 31, wq = q >> 5;
        int oc = (p >> 3) * 128 + (int)rank * 64 + wq * 8 + (p & 7);
        float4 v = *reinterpret_cast<const float4*>(Whh + (size_t)oc * F + k4 * 4);
        uint4 s;
        s.x = f2tf(v.x); s.y = f2tf(v.y); s.z = f2tf(v.z); s.w = f2tf(v.w);
        *reinterpret_cast<uint4*>(Wc + q * PW2 + k4 * 4) = s;
    }
    __syncthreads();
    CLUSTER_SYNC();

    // This thread's original P columns for each gate (nj == gate)
    int ocb[4];
#pragma unroll
    for (int nj = 0; nj < 4; ++nj)
        ocb[nj] = nj * 128 + (int)rank * 64 + w * 8 + 2 * tig;
    // This thread's unit column in Hs (global 0..127)
    const int ucol = (int)rank * 64 + w * 8 + 2 * tig;

    float4 cst[4];
#pragma unroll
    for (int mi = 0; mi < 4; ++mi) cst[mi] = make_float4(0.f, 0.f, 0.f, 0.f);

    // Prefetch P-gather for t=0
    float4 pf[4][4];
#pragma unroll
    for (int mi = 0; mi < 4; ++mi) {
        int r0 = mi * 16 + gid;
        const float* P0 = g_P + (size_t)Nb[r0 * 17 + 0] * G4;
        const float* P1 = g_P + (size_t)Nb[(r0 + 8) * 17 + 0] * G4;
#pragma unroll
        for (int nj = 0; nj < 4; ++nj) {
            float2 u = *reinterpret_cast<const float2*>(P0 + ocb[nj]);
            float2 v = *reinterpret_cast<const float2*>(P1 + ocb[nj]);
            pf[mi][nj] = make_float4(u.x, u.y, v.x, v.y);
        }
    }

#pragma unroll 1
    for (int t = 0; t < DEG; ++t) {
        float4 acc[4][4];
#pragma unroll
        for (int mi = 0; mi < 4; ++mi)
#pragma unroll
            for (int nj = 0; nj < 4; ++nj) acc[mi][nj] = pf[mi][nj];

        // Prefetch next step's P while the GEMM runs
        if (t + 1 < DEG) {
#pragma unroll
            for (int mi = 0; mi < 4; ++mi) {
                int r0 = mi * 16 + gid;
                const float* P0 = g_P + (size_t)Nb[r0 * 17 + t + 1] * G4;
                const float* P1 = g_P + (size_t)Nb[(r0 + 8) * 17 + t + 1] * G4;
#pragma unroll
                for (int nj = 0; nj < 4; ++nj) {
                    float2 u = *reinterpret_cast<const float2*>(P0 + ocb[nj]);
                    float2 v = *reinterpret_cast<const float2*>(P1 + ocb[nj]);
                    pf[mi][nj] = make_float4(u.x, u.y, v.x, v.y);
                }
            }
        }

        if (t > 0) {
            const uint32_t* hb = HsB + ((t - 1) & 1) * R_HSBUF;
#pragma unroll 4
            for (int k8 = 0; k8 < 16; ++k8) {
                uint32_t bb[4][2];
#pragma unroll
                for (int nj = 0; nj < 4; ++nj) {
                    const uint32_t* bp = Wc + (w * 32 + nj * 8 + gid) * PW2 + k8 * 8 + tig;
                    bb[nj][0] = bp[0];
                    bb[nj][1] = bp[4];
                }
#pragma unroll
                for (int mi = 0; mi < 4; ++mi) {
                    const uint32_t* ap = hb + (mi * 16 + gid) * PH2 + k8 * 8 + tig;
                    uint32_t a0 = ap[0], a1 = ap[8 * PH2], a2 = ap[4], a3 = ap[8 * PH2 + 4];
#pragma unroll
                    for (int nj = 0; nj < 4; ++nj)
                        mma8(acc[mi][nj], a0, a1, a2, a3, bb[nj][0], bb[nj][1]);
                }
            }
        }

        // Before the extra fp32 h-store into buf0 at the final step, make sure
        // the peer is done reading buf0 in its t=15 GEMM.
        if (t == DEG - 1) CLUSTER_SYNC();

        // LSTM cell (nj = gate: 0=i,1=f,2=g,3=o), warp-local, then write h half
        uint32_t* hw = HsB + (t & 1) * R_HSBUF;
        const uint32_t remBase = peerHsByte + (((t & 1) * R_HSBUF) << 2);
#pragma unroll
        for (int mi = 0; mi < 4; ++mi) {
            int r0 = mi * 16 + gid, r1 = r0 + 8;
            float4 I = acc[mi][0], Fg = acc[mi][1], G = acc[mi][2], O = acc[mi][3];
            float4 C = cst[mi];
            float cx = fmaf(sigm_f(Fg.x), C.x, sigm_f(I.x) * tanh_f(G.x));
            float cy = fmaf(sigm_f(Fg.y), C.y, sigm_f(I.y) * tanh_f(G.y));
            float cz = fmaf(sigm_f(Fg.z), C.z, sigm_f(I.z) * tanh_f(G.z));
            float cw = fmaf(sigm_f(Fg.w), C.w, sigm_f(I.w) * tanh_f(G.w));
            cst[mi] = make_float4(cx, cy, cz, cw);
            float h00 = sigm_f(O.x) * tanh_f(cx);
            float h01 = sigm_f(O.y) * tanh_f(cy);
            float h10 = sigm_f(O.z) * tanh_f(cz);
            float h11 = sigm_f(O.w) * tanh_f(cw);

            unsigned long long p0 = (unsigned long long)f2tf(h00)
                                  | ((unsigned long long)f2tf(h01) << 32);
            unsigned long long p1 = (unsigned long long)f2tf(h10)
                                  | ((unsigned long long)f2tf(h11) << 32);
            int o0 = r0 * PH2 + ucol, o1 = r1 * PH2 + ucol;
            *reinterpret_cast<unsigned long long*>(hw + o0) = p0;
            *reinterpret_cast<unsigned long long*>(hw + o1) = p1;
            st_dsmem64(remBase + (o0 << 2), p0);
            st_dsmem64(remBase + (o1 << 2), p1);

            if (t == DEG - 1) {   // fp32 copy of final h into buf0 (for epilogues)
                unsigned long long q0 = (unsigned long long)__float_as_uint(h00)
                                      | ((unsigned long long)__float_as_uint(h01) << 32);
                unsigned long long q1 = (unsigned long long)__float_as_uint(h10)
                                      | ((unsigned long long)__float_as_uint(h11) << 32);
                *reinterpret_cast<unsigned long long*>(HsB + o0) = q0;
                *reinterpret_cast<unsigned long long*>(HsB + o1) = q1;
                st_dsmem64(peerHsByte + (o0 << 2), q0);
                st_dsmem64(peerHsByte + (o1 << 2), q1);
            }
        }
        CLUSTER_SYNC();
    }

    // buf0 = full final h in fp32 (both halves, via DSMEM exchange)
    const float* hs0 = reinterpret_cast<const float*>(HsB);
    float* Wcf = reinterpret_cast<float*>(Wc);
    const int nl0 = w * 8;

    if (LAYER == 1) {
        float oacc[8][2];
#pragma unroll
        for (int uu = 0; uu < 2; ++uu) {
            float b0 = __ldg(bneigh + (int)rank * 64 + uu * 32 + lane);
#pragma unroll
            for (int i = 0; i < 8; ++i) oacc[i][uu] = b0;
        }
        // self term: X rows (global), Wself rows rank*64..+63
        __syncthreads();
        for (int idx = tid; idx < 64 * 32; idx += NT) {
            int row = idx >> 5, k4 = idx & 31;
            *reinterpret_cast<float4*>(Wcf + row * PH2 + k4 * 4) =
                *reinterpret_cast<const float4*>(Wself + (size_t)((int)rank * 64 + row) * F + k4 * 4);
        }
        __syncthreads();
#pragma unroll 2
        for (int k4 = 0; k4 < 32; ++k4) {
            float4 a[8];
#pragma unroll
            for (int i = 0; i < 8; ++i) {
                int n = tile0 + nl0 + i;
                a[i] = (n < NN) ? *reinterpret_cast<const float4*>(X + (size_t)n * F + k4 * 4)
                                : make_float4(0.f, 0.f, 0.f, 0.f);
            }
#pragma unroll
            for (int uu = 0; uu < 2; ++uu) {
                float4 b = *reinterpret_cast<const float4*>(Wcf + (uu * 32 + lane) * PH2 + k4 * 4);
#pragma unroll
                for (int i = 0; i < 8; ++i)
                    oacc[i][uu] = fmaf(a[i].x, b.x, fmaf(a[i].y, b.y,
                                  fmaf(a[i].z, b.z, fmaf(a[i].w, b.w, oacc[i][uu]))));
            }
        }
        // neighbor term: final h (fp32) x Wneigh rows rank*64..+63
        __syncthreads();
        for (int idx = tid; idx < 64 * 32; idx += NT) {
            int row = idx >> 5, k4 = idx & 31;
            *reinterpret_cast<float4*>(Wcf + row * PH2 + k4 * 4) =
                *reinterpret_cast<const float4*>(Wneigh + (size_t)((int)rank * 64 + row) * F + k4 * 4);
        }
        __syncthreads();
#pragma unroll 2
        for (int k4 = 0; k4 < 32; ++k4) {
            float4 a[8];
#pragma unroll
            for (int i = 0; i < 8; ++i)
                a[i] = *reinterpret_cast<const float4*>(hs0 + (nl0 + i) * PH2 + k4 * 4);
#pragma unroll
            for (int uu = 0; uu < 2; ++uu) {
                float4 b = *reinterpret_cast<const float4*>(Wcf + (uu * 32 + lane) * PH2 + k4 * 4);
#pragma unroll
                for (int i = 0; i < 8; ++i)
                    oacc[i][uu] = fmaf(a[i].x, b.x, fmaf(a[i].y, b.y,
                                  fmaf(a[i].z, b.z, fmaf(a[i].w, b.w, oacc[i][uu]))));
            }
        }
#pragma unroll
        for (int i = 0; i < 8; ++i) {
            int n = tile0 + nl0 + i;
            if (n < NN) {
#pragma unroll
                for (int uu = 0; uu < 2; ++uu)
                    g_H1[(size_t)n * F + (int)rank * 64 + uu * 32 + lane] =
                        fmaxf(oacc[i][uu], 0.0f);
            }
        }
    } else {
        if (rank == 0) {   // buf0 holds full h locally; rank 0 computes the tile
            float part[8];
#pragma unroll
            for (int i = 0; i < 8; ++i) part[i] = 0.0f;
#pragma unroll
            for (int uu = 0; uu < 4; ++uu) {
                int u = uu * 32 + lane;
                float wn = __ldg(Wneigh + u);
                float ws = __ldg(Wself + u);
#pragma unroll
                for (int i = 0; i < 8; ++i) {
                    int n = tile0 + nl0 + i;
                    float hx = hs0[(nl0 + i) * PH2 + u];
                    float xx = (n < NN) ? __ldg(X + (size_t)n * F + u) : 0.0f;
                    part[i] = fmaf(hx, wn, fmaf(xx, ws, part[i]));
                }
            }
            float b0 = __ldg(bneigh);
#pragma unroll
            for (int off = 16; off > 0; off >>= 1)
#pragma unroll
                for (int i = 0; i < 8; ++i)
                    part[i] += __shfl_xor_sync(0xffffffffu, part[i], off);
            if (lane == 0) {
#pragma unroll
                for (int i = 0; i < 8; ++i) {
                    int n = tile0 + nl0 + i;
                    if (n < NN) out[n] = sigm_p(part[i] + b0);
                }
            }
        }
    }
}

extern "C" void kernel_launch(void* const* d_in, const int* in_sizes, int n_in,
                              void* d_out, int out_size) {
    const float* x       = (const float*)d_in[0];
    const int*   nbr     = (const int*)  d_in[1];
    const float* Wih1    = (const float*)d_in[2];
    const float* Whh1    = (const float*)d_in[3];
    const float* bih1    = (const float*)d_in[4];
    const float* bhh1    = (const float*)d_in[5];
    const float* Wself1  = (const float*)d_in[6];
    const float* Wneigh1 = (const float*)d_in[7];
    const float* bneigh1 = (const float*)d_in[8];
    const float* Wih2    = (const float*)d_in[9];
    const float* Whh2    = (const float*)d_in[10];
    const float* bih2    = (const float*)d_in[11];
    const float* bhh2    = (const float*)d_in[12];
    const float* Wself2  = (const float*)d_in[13];
    const float* Wneigh2 = (const float*)d_in[14];
    const float* bneigh2 = (const float*)d_in[15];
    float* out = (float*)d_out;

    const int nbp = (NN + TILE - 1) / TILE;   // 313 proj blocks
    const int nbr_grid = nbp * 2;             // 626 rec CTAs (313 clusters of 2)

    cudaFuncSetAttribute(proj_kernel,   cudaFuncAttributeMaxDynamicSharedMemorySize, P_SMEM_BYTES);
    cudaFuncSetAttribute(rec_kernel<1>, cudaFuncAttributeMaxDynamicSharedMemorySize, R_BYTES);
    cudaFuncSetAttribute(rec_kernel<2>, cudaFuncAttributeMaxDynamicSharedMemorySize, R_BYTES);

    proj_kernel<<<nbp, NT, P_SMEM_BYTES>>>(x, 0, Wih1, bih1, bhh1);
    rec_kernel<1><<<nbr_grid, NT, R_BYTES>>>(x, nbr, Whh1, Wself1, Wneigh1, bneigh1, nullptr);
    proj_kernel<<<nbp, NT, P_SMEM_BYTES>>>(nullptr, 1, Wih2, bih2, bhh2);
    rec_kernel<2><<<nbr_grid, NT, R_BYTES>>>(nullptr, nbr, Whh2, Wself2, Wneigh2, bneigh2, out);
}

// round 10
// speedup vs baseline: 8.7290x; 1.6218x over previous
#include <cuda_runtime.h>
#include <cuda_bf16.h>
#include <math.h>
#include <stdint.h>

// Problem constants
#define NN    20000
#define DEG   16
#define F     128
#define G4    512
#define TILE  64
#define NT    256

// ---------------- proj kernel layout (unchanged, tf32) ----------------
#define PH    132
#define PW    68
#define P_SH_HS 0
#define P_SH_WC (TILE*PH + TILE*17)            // 9536
#define P_SMEM_FLOATS (P_SH_WC + G4*PW)        // 44352
#define P_SMEM_BYTES  (P_SMEM_FLOATS*4)        // 177408

// ---------------- rec kernel (2-CTA cluster, bf16) layout, u32 units -----
#define PB    68      // bf16x2 pitch (u32): Wc rows (64 u32 data) / Hs rows (32 u32 data)
#define PE    132     // fp32 pitch for epilogue weights + final-h
#define R_NB  0                                // 64*17 ints = 1088
#define R_HS  (TILE*17)                        // 1088
#define R_HSBUF (TILE*PB)                      // 4352 u32 per buffer
#define R_WC  (R_HS + 2*R_HSBUF)               // 9792
#define R_TOTAL (R_WC + 256*PB)                // 27200 u32
#define R_BYTES (R_TOTAL*4)                    // 108800 B  -> 2 CTAs/SM

__device__ float g_P [(size_t)NN * G4];   // projections + bias (fp32, exact)
__device__ float g_H1[(size_t)NN * F];    // layer-1 output

// ---------------- helpers ----------------
__device__ __forceinline__ uint32_t f2tf(float f) {
    uint32_t u; asm("cvt.rna.tf32.f32 %0, %1;" : "=r"(u) : "f"(f)); return u;
}
__device__ __forceinline__ uint32_t packbf(float lo, float hi) {
    uint32_t r; asm("cvt.rn.bf16x2.f32 %0, %1, %2;" : "=r"(r) : "f"(hi), "f"(lo));
    return r;
}
__device__ __forceinline__ void mma8(float4& d, uint32_t a0, uint32_t a1, uint32_t a2,
                                     uint32_t a3, uint32_t b0, uint32_t b1) {
    asm volatile(
        "mma.sync.aligned.m16n8k8.row.col.f32.tf32.tf32.f32 "
        "{%0,%1,%2,%3}, {%4,%5,%6,%7}, {%8,%9}, {%0,%1,%2,%3};"
        : "+f"(d.x), "+f"(d.y), "+f"(d.z), "+f"(d.w)
        : "r"(a0), "r"(a1), "r"(a2), "r"(a3), "r"(b0), "r"(b1));
}
__device__ __forceinline__ void mma16(float4& d, uint32_t a0, uint32_t a1, uint32_t a2,
                                      uint32_t a3, uint32_t b0, uint32_t b1) {
    asm volatile(
        "mma.sync.aligned.m16n8k16.row.col.f32.bf16.bf16.f32 "
        "{%0,%1,%2,%3}, {%4,%5,%6,%7}, {%8,%9}, {%0,%1,%2,%3};"
        : "+f"(d.x), "+f"(d.y), "+f"(d.z), "+f"(d.w)
        : "r"(a0), "r"(a1), "r"(a2), "r"(a3), "r"(b0), "r"(b1));
}
__device__ __forceinline__ float sigm_f(float x) {
    float y, h = 0.5f * x;
    asm("tanh.approx.f32 %0, %1;" : "=f"(y) : "f"(h));
    return fmaf(0.5f, y, 0.5f);
}
__device__ __forceinline__ float tanh_f(float x) {
    float y; asm("tanh.approx.f32 %0, %1;" : "=f"(y) : "f"(x)); return y;
}
__device__ __forceinline__ float sigm_p(float x) { return 1.0f / (1.0f + __expf(-x)); }

__device__ __forceinline__ uint32_t ctarank() {
    uint32_t r; asm("mov.u32 %0, %%cluster_ctarank;" : "=r"(r)); return r;
}
__device__ __forceinline__ uint32_t smem_u32(const void* p) {
    uint32_t a;
    asm("{ .reg .u64 t; cvta.to.shared.u64 t, %1; cvt.u32.u64 %0, t; }" : "=r"(a) : "l"(p));
    return a;
}
__device__ __forceinline__ uint32_t mapa_u32(uint32_t addr, uint32_t rank) {
    uint32_t r; asm("mapa.shared::cluster.u32 %0, %1, %2;" : "=r"(r) : "r"(addr), "r"(rank));
    return r;
}
__device__ __forceinline__ void st_dsmem32(uint32_t addr, uint32_t v) {
    asm volatile("st.shared::cluster.u32 [%0], %1;" :: "r"(addr), "r"(v) : "memory");
}
__device__ __forceinline__ void st_dsmem64(uint32_t addr, unsigned long long v) {
    asm volatile("st.shared::cluster.u64 [%0], %1;" :: "r"(addr), "l"(v) : "memory");
}
#define CLUSTER_SYNC() do { \
    asm volatile("barrier.cluster.arrive.aligned;" ::: "memory"); \
    asm volatile("barrier.cluster.wait.aligned;" ::: "memory"); } while (0)

// ===========================================================================
// proj: g_P[n][col] = X[n] @ Wih[col] + bih[col] + bhh[col]   (tf32, exact-ish)
// ===========================================================================
__device__ __forceinline__ void stage_w_tf32(uint32_t* Wc, const float* __restrict__ W, int k0) {
    for (int idx = threadIdx.x; idx < G4 * 16; idx += NT) {
        int q = idx >> 4, k4 = idx & 15;
        float4 v = *reinterpret_cast<const float4*>(W + (size_t)q * F + k0 + k4 * 4);
        uint4 s;
        s.x = f2tf(v.x); s.y = f2tf(v.y); s.z = f2tf(v.z); s.w = f2tf(v.w);
        *reinterpret_cast<uint4*>(Wc + q * PW + k4 * 4) = s;
    }
}

__device__ __forceinline__ void gemm64p(float4 (&acc)[4][8], const uint32_t* __restrict__ Wc,
                                        const float* __restrict__ Hs, int kbase,
                                        int gid, int tig, int wslice) {
#pragma unroll
    for (int k8 = 0; k8 < 8; ++k8) {
        uint32_t bb[8][2];
#pragma unroll
        for (int nj = 0; nj < 8; ++nj) {
            const uint32_t* bp = Wc + (wslice + nj * 8 + gid) * PW + k8 * 8 + tig;
            bb[nj][0] = bp[0];
            bb[nj][1] = bp[4];
        }
#pragma unroll
        for (int mi = 0; mi < 4; ++mi) {
            const float* ap = Hs + (mi * 16 + gid) * PH + kbase + k8 * 8 + tig;
            uint32_t a0 = f2tf(ap[0]);
            uint32_t a1 = f2tf(ap[8 * PH]);
            uint32_t a2 = f2tf(ap[4]);
            uint32_t a3 = f2tf(ap[8 * PH + 4]);
#pragma unroll
            for (int nj = 0; nj < 8; ++nj)
                mma8(acc[mi][nj], a0, a1, a2, a3, bb[nj][0], bb[nj][1]);
        }
    }
}

__global__ void __launch_bounds__(NT, 1)
proj_kernel(const float* __restrict__ Xin, int useH1,
            const float* __restrict__ Wih,
            const float* __restrict__ bih, const float* __restrict__ bhh) {
    extern __shared__ float smem[];
    float* Hs = smem + P_SH_HS;
    uint32_t* Wc = reinterpret_cast<uint32_t*>(smem + P_SH_WC);

    const float* X = useH1 ? g_H1 : Xin;
    const int tid = threadIdx.x, lane = tid & 31, w = tid >> 5;
    const int gid = lane >> 2, tig = lane & 3;
    const int tile0 = blockIdx.x * TILE;

    for (int idx = tid; idx < TILE * 32; idx += NT) {
        int r = idx >> 5, c4 = idx & 31;
        int n = tile0 + r;
        float4 v = make_float4(0.f, 0.f, 0.f, 0.f);
        if (n < NN) v = *reinterpret_cast<const float4*>(X + (size_t)n * F + c4 * 4);
        *reinterpret_cast<float4*>(Hs + r * PH + c4 * 4) = v;
    }

    float4 acc[4][8];
#pragma unroll
    for (int nj = 0; nj < 8; ++nj) {
        int col = w * 64 + nj * 8 + 2 * tig;
        float b0 = __ldg(bih + col) + __ldg(bhh + col);
        float b1 = __ldg(bih + col + 1) + __ldg(bhh + col + 1);
#pragma unroll
        for (int mi = 0; mi < 4; ++mi) acc[mi][nj] = make_float4(b0, b1, b0, b1);
    }

#pragma unroll 1
    for (int c2 = 0; c2 < 2; ++c2) {
        __syncthreads();
        stage_w_tf32(Wc, Wih, c2 * 64);
        __syncthreads();
        gemm64p(acc, Wc, Hs, c2 * 64, gid, tig, w * 64);
    }

#pragma unroll
    for (int mi = 0; mi < 4; ++mi) {
        int r0 = mi * 16 + gid;
        int n0 = tile0 + r0, n1 = n0 + 8;
#pragma unroll
        for (int nj = 0; nj < 8; ++nj) {
            int col = w * 64 + nj * 8 + 2 * tig;
            if (n0 < NN)
                *reinterpret_cast<float2*>(g_P + (size_t)n0 * G4 + col) =
                    make_float2(acc[mi][nj].x, acc[mi][nj].y);
            if (n1 < NN)
                *reinterpret_cast<float2*>(g_P + (size_t)n1 * G4 + col) =
                    make_float2(acc[mi][nj].z, acc[mi][nj].w);
        }
    }
}

// ===========================================================================
// rec: 2-CTA cluster, bf16 m16n8k16, Whh slice resident (68 KB), 2 CTAs/SM.
// Gather P (fp32, exact) directly into mma accumulators each step.
// ===========================================================================
template <int LAYER>
__global__ void __launch_bounds__(NT, 2) __cluster_dims__(2, 1, 1)
rec_kernel(const float* __restrict__ Xin, const int* __restrict__ nbr,
           const float* __restrict__ Whh, const float* __restrict__ Wself,
           const float* __restrict__ Wneigh, const float* __restrict__ bneigh,
           float* __restrict__ out) {
    extern __shared__ uint32_t smemU[];
    int*       Nb  = reinterpret_cast<int*>(smemU + R_NB);
    uint32_t*  HsB = smemU + R_HS;                 // 2 x [64][PB] bf16x2; fp32 final-h @ pitch PE
    uint32_t*  Wc  = smemU + R_WC;                 // 256 x PB bf16x2 (resident Whh slice)

    const float* X = (LAYER == 1) ? Xin : g_H1;
    const int tid = threadIdx.x, lane = tid & 31, w = tid >> 5;
    const int gid = lane >> 2, tig = lane & 3;
    const uint32_t rank = ctarank();
    const int tile0 = (blockIdx.x >> 1) * TILE;

    const uint32_t myHsByte = smem_u32(HsB);
    const uint32_t peerHsByte = mapa_u32(myHsByte, rank ^ 1u);

    // Stage neighbor indices
    for (int idx = tid; idx < TILE * DEG; idx += NT) {
        int r = idx >> 4, t = idx & 15;
        int n = tile0 + r;
        Nb[r * 17 + t] = (n < NN) ? __ldg(nbr + (size_t)n * DEG + t) : 0;
    }
    // Stage this CTA's 256-col permuted Whh slice in bf16 (ONCE).
    for (int idx = tid; idx < 256 * 32; idx += NT) {
        int q = idx >> 5, k4 = idx & 31;
        int p = q & 31, wq = q >> 5;
        int oc = (p >> 3) * 128 + (int)rank * 64 + wq * 8 + (p & 7);
        float4 v = *reinterpret_cast<const float4*>(Whh + (size_t)oc * F + k4 * 4);
        *reinterpret_cast<uint2*>(Wc + q * PB + k4 * 2) =
            make_uint2(packbf(v.x, v.y), packbf(v.z, v.w));
    }
    __syncthreads();
    CLUSTER_SYNC();

    // This thread's original P columns per gate (nj == gate)
    int ocb[4];
#pragma unroll
    for (int nj = 0; nj < 4; ++nj)
        ocb[nj] = nj * 128 + (int)rank * 64 + w * 8 + 2 * tig;
    const int ucolU = (int)rank * 32 + w * 4 + tig;     // bf16x2 u32 col in Hs
    const int ucolF = (int)rank * 64 + w * 8 + 2 * tig; // fp32 col (final h)

    float4 cst[4];
#pragma unroll
    for (int mi = 0; mi < 4; ++mi) cst[mi] = make_float4(0.f, 0.f, 0.f, 0.f);

#pragma unroll 1
    for (int t = 0; t < DEG; ++t) {
        // Gather P straight into accumulators (LDGs overlap the GEMM below)
        float4 acc[4][4];
#pragma unroll
        for (int mi = 0; mi < 4; ++mi) {
            int r0 = mi * 16 + gid;
            const float* P0 = g_P + (size_t)Nb[r0 * 17 + t] * G4;
            const float* P1 = g_P + (size_t)Nb[(r0 + 8) * 17 + t] * G4;
#pragma unroll
            for (int nj = 0; nj < 4; ++nj) {
                float2 u = *reinterpret_cast<const float2*>(P0 + ocb[nj]);
                float2 v = *reinterpret_cast<const float2*>(P1 + ocb[nj]);
                acc[mi][nj] = make_float4(u.x, u.y, v.x, v.y);
            }
        }

        if (t > 0) {
            const uint32_t* hb = HsB + ((t - 1) & 1) * R_HSBUF;
#pragma unroll 4
            for (int k16 = 0; k16 < 8; ++k16) {
                uint32_t bb[4][2];
#pragma unroll
                for (int nj = 0; nj < 4; ++nj) {
                    const uint32_t* bp = Wc + (w * 32 + nj * 8 + gid) * PB + k16 * 8 + tig;
                    bb[nj][0] = bp[0];
                    bb[nj][1] = bp[4];
                }
#pragma unroll
                for (int mi = 0; mi < 4; ++mi) {
                    const uint32_t* ap = hb + (mi * 16 + gid) * PB + k16 * 8 + tig;
                    uint32_t a0 = ap[0], a1 = ap[8 * PB], a2 = ap[4], a3 = ap[8 * PB + 4];
#pragma unroll
                    for (int nj = 0; nj < 4; ++nj)
                        mma16(acc[mi][nj], a0, a1, a2, a3, bb[nj][0], bb[nj][1]);
                }
            }
        }

        // Before overwriting with the fp32 final-h (pitch PE spans both buffers),
        // ensure the peer finished its t=15 GEMM reads of buf0.
        if (t == DEG - 1) CLUSTER_SYNC();

        uint32_t* hw = HsB + (t & 1) * R_HSBUF;
        const uint32_t remBase = peerHsByte + (((t & 1) * R_HSBUF) << 2);
#pragma unroll
        for (int mi = 0; mi < 4; ++mi) {
            int r0 = mi * 16 + gid, r1 = r0 + 8;
            float4 I = acc[mi][0], Fg = acc[mi][1], G = acc[mi][2], O = acc[mi][3];
            float4 C = cst[mi];
            float cx = fmaf(sigm_f(Fg.x), C.x, sigm_f(I.x) * tanh_f(G.x));
            float cy = fmaf(sigm_f(Fg.y), C.y, sigm_f(I.y) * tanh_f(G.y));
            float cz = fmaf(sigm_f(Fg.z), C.z, sigm_f(I.z) * tanh_f(G.z));
            float cw = fmaf(sigm_f(Fg.w), C.w, sigm_f(I.w) * tanh_f(G.w));
            cst[mi] = make_float4(cx, cy, cz, cw);
            float h00 = sigm_f(O.x) * tanh_f(cx);
            float h01 = sigm_f(O.y) * tanh_f(cy);
            float h10 = sigm_f(O.z) * tanh_f(cz);
            float h11 = sigm_f(O.w) * tanh_f(cw);

            if (t < DEG - 1) {
                uint32_t p0 = packbf(h00, h01), p1 = packbf(h10, h11);
                int o0 = r0 * PB + ucolU, o1 = r1 * PB + ucolU;
                hw[o0] = p0;
                hw[o1] = p1;
                st_dsmem32(remBase + (o0 << 2), p0);
                st_dsmem32(remBase + (o1 << 2), p1);
            } else {
                // fp32 final h at pitch PE spanning both buffers (for epilogues)
                unsigned long long q0 = (unsigned long long)__float_as_uint(h00)
                                      | ((unsigned long long)__float_as_uint(h01) << 32);
                unsigned long long q1 = (unsigned long long)__float_as_uint(h10)
                                      | ((unsigned long long)__float_as_uint(h11) << 32);
                int o0 = r0 * PE + ucolF, o1 = r1 * PE + ucolF;
                *reinterpret_cast<unsigned long long*>(HsB + o0) = q0;
                *reinterpret_cast<unsigned long long*>(HsB + o1) = q1;
                st_dsmem64(peerHsByte + (o0 << 2), q0);
                st_dsmem64(peerHsByte + (o1 << 2), q1);
            }
        }
        CLUSTER_SYNC();
    }

    // HsB = full final h in fp32, pitch PE (both halves exchanged via DSMEM)
    const float* hs0 = reinterpret_cast<const float*>(HsB);
    float* Wcf = reinterpret_cast<float*>(Wc);   // epilogue fp32 weights, pitch PE
    const int nl0 = w * 8;

    if (LAYER == 1) {
        float oacc[8][2];
#pragma unroll
        for (int uu = 0; uu < 2; ++uu) {
            float b0 = __ldg(bneigh + (int)rank * 64 + uu * 32 + lane);
#pragma unroll
            for (int i = 0; i < 8; ++i) oacc[i][uu] = b0;
        }
        // self term: X rows (global) x Wself rows rank*64..+63
        __syncthreads();
        for (int idx = tid; idx < 64 * 32; idx += NT) {
            int row = idx >> 5, k4 = idx & 31;
            *reinterpret_cast<float4*>(Wcf + row * PE + k4 * 4) =
                *reinterpret_cast<const float4*>(Wself + (size_t)((int)rank * 64 + row) * F + k4 * 4);
        }
        __syncthreads();
#pragma unroll 2
        for (int k4 = 0; k4 < 32; ++k4) {
            float4 a[8];
#pragma unroll
            for (int i = 0; i < 8; ++i) {
                int n = tile0 + nl0 + i;
                a[i] = (n < NN) ? *reinterpret_cast<const float4*>(X + (size_t)n * F + k4 * 4)
                                : make_float4(0.f, 0.f, 0.f, 0.f);
            }
#pragma unroll
            for (int uu = 0; uu < 2; ++uu) {
                float4 b = *reinterpret_cast<const float4*>(Wcf + (uu * 32 + lane) * PE + k4 * 4);
#pragma unroll
                for (int i = 0; i < 8; ++i)
                    oacc[i][uu] = fmaf(a[i].x, b.x, fmaf(a[i].y, b.y,
                                  fmaf(a[i].z, b.z, fmaf(a[i].w, b.w, oacc[i][uu]))));
            }
        }
        // neighbor term: final h (fp32) x Wneigh rows rank*64..+63
        __syncthreads();
        for (int idx = tid; idx < 64 * 32; idx += NT) {
            int row = idx >> 5, k4 = idx & 31;
            *reinterpret_cast<float4*>(Wcf + row * PE + k4 * 4) =
                *reinterpret_cast<const float4*>(Wneigh + (size_t)((int)rank * 64 + row) * F + k4 * 4);
        }
        __syncthreads();
#pragma unroll 2
        for (int k4 = 0; k4 < 32; ++k4) {
            float4 a[8];
#pragma unroll
            for (int i = 0; i < 8; ++i)
                a[i] = *reinterpret_cast<const float4*>(hs0 + (nl0 + i) * PE + k4 * 4);
#pragma unroll
            for (int uu = 0; uu < 2; ++uu) {
                float4 b = *reinterpret_cast<const float4*>(Wcf + (uu * 32 + lane) * PE + k4 * 4);
#pragma unroll
                for (int i = 0; i < 8; ++i)
                    oacc[i][uu] = fmaf(a[i].x, b.x, fmaf(a[i].y, b.y,
                                  fmaf(a[i].z, b.z, fmaf(a[i].w, b.w, oacc[i][uu]))));
            }
        }
#pragma unroll
        for (int i = 0; i < 8; ++i) {
            int n = tile0 + nl0 + i;
            if (n < NN) {
#pragma unroll
                for (int uu = 0; uu < 2; ++uu)
                    g_H1[(size_t)n * F + (int)rank * 64 + uu * 32 + lane] =
                        fmaxf(oacc[i][uu], 0.0f);
            }
        }
    } else {
        if (rank == 0) {
            float part[8];
#pragma unroll
            for (int i = 0; i < 8; ++i) part[i] = 0.0f;
#pragma unroll
            for (int uu = 0; uu < 4; ++uu) {
                int u = uu * 32 + lane;
                float wn = __ldg(Wneigh + u);
                float ws = __ldg(Wself + u);
#pragma unroll
                for (int i = 0; i < 8; ++i) {
                    int n = tile0 + nl0 + i;
                    float hx = hs0[(nl0 + i) * PE + u];
                    float xx = (n < NN) ? __ldg(X + (size_t)n * F + u) : 0.0f;
                    part[i] = fmaf(hx, wn, fmaf(xx, ws, part[i]));
                }
            }
            float b0 = __ldg(bneigh);
#pragma unroll
            for (int off = 16; off > 0; off >>= 1)
#pragma unroll
                for (int i = 0; i < 8; ++i)
                    part[i] += __shfl_xor_sync(0xffffffffu, part[i], off);
            if (lane == 0) {
#pragma unroll
                for (int i = 0; i < 8; ++i) {
                    int n = tile0 + nl0 + i;
                    if (n < NN) out[n] = sigm_p(part[i] + b0);
                }
            }
        }
    }
}

extern "C" void kernel_launch(void* const* d_in, const int* in_sizes, int n_in,
                              void* d_out, int out_size) {
    const float* x       = (const float*)d_in[0];
    const int*   nbr     = (const int*)  d_in[1];
    const float* Wih1    = (const float*)d_in[2];
    const float* Whh1    = (const float*)d_in[3];
    const float* bih1    = (const float*)d_in[4];
    const float* bhh1    = (const float*)d_in[5];
    const float* Wself1  = (const float*)d_in[6];
    const float* Wneigh1 = (const float*)d_in[7];
    const float* bneigh1 = (const float*)d_in[8];
    const float* Wih2    = (const float*)d_in[9];
    const float* Whh2    = (const float*)d_in[10];
    const float* bih2    = (const float*)d_in[11];
    const float* bhh2    = (const float*)d_in[12];
    const float* Wself2  = (const float*)d_in[13];
    const float* Wneigh2 = (const float*)d_in[14];
    const float* bneigh2 = (const float*)d_in[15];
    float* out = (float*)d_out;

    const int nbp = (NN + TILE - 1) / TILE;   // 313 proj blocks
    const int nbr_grid = nbp * 2;             // 626 rec CTAs (313 clusters of 2)

    cudaFuncSetAttribute(proj_kernel,   cudaFuncAttributeMaxDynamicSharedMemorySize, P_SMEM_BYTES);
    cudaFuncSetAttribute(rec_kernel<1>, cudaFuncAttributeMaxDynamicSharedMemorySize, R_BYTES);
    cudaFuncSetAttribute(rec_kernel<2>, cudaFuncAttributeMaxDynamicSharedMemorySize, R_BYTES);

    proj_kernel<<<nbp, NT, P_SMEM_BYTES>>>(x, 0, Wih1, bih1, bhh1);
    rec_kernel<1><<<nbr_grid, NT, R_BYTES>>>(x, nbr, Whh1, Wself1, Wneigh1, bneigh1, nullptr);
    proj_kernel<<<nbp, NT, P_SMEM_BYTES>>>(nullptr, 1, Wih2, bih2, bhh2);
    rec_kernel<2><<<nbr_grid, NT, R_BYTES>>>(nullptr, nbr, Whh2, Wself2, Wneigh2, bneigh2, out);
}